// round 15
// baseline (speedup 1.0000x reference)
#include <cuda_runtime.h>
#include <cuda_fp16.h>
#include <cstdint>
#include <cmath>

// Problem constants
#define BATCH 64
#define TSTEPS 512
#define DIM 1024
#define OUTD 1024
#define M_TOTAL (BATCH * TSTEPS)   // 32768
#define NCHUNKS 8                  // N / BN

// Scratch (device globals: no allocations allowed)
__device__ __half g_Xh[(size_t)M_TOTAL * DIM];   // fp16 copy of inputs (64 MB)
__device__ __half g_UhT[(size_t)OUTD * DIM];     // Ua transposed, fp16 [n][k]
__device__ float g_WaS[BATCH * OUTD];            // prev@Wa + Ba
__device__ float g_partial[M_TOTAL * NCHUNKS];   // per-(row, n-chunk) partial

__device__ __forceinline__ uint32_t pack_f16x2(float lo, float hi) {
    uint32_t r;
    asm("cvt.rn.f16x2.f32 %0, %1, %2;" : "=r"(r) : "f"(hi), "f"(lo));
    return r;
}
__device__ __forceinline__ void mma_f16(float* c, const uint32_t* a, const uint32_t* b) {
    asm("mma.sync.aligned.m16n8k16.row.col.f32.f16.f16.f32 "
        "{%0,%1,%2,%3}, {%4,%5,%6,%7}, {%8,%9}, {%0,%1,%2,%3};"
        : "+f"(c[0]), "+f"(c[1]), "+f"(c[2]), "+f"(c[3])
        : "r"(a[0]), "r"(a[1]), "r"(a[2]), "r"(a[3]), "r"(b[0]), "r"(b[1]));
}
__device__ __forceinline__ void ldsm_x4(uint32_t& r0, uint32_t& r1,
                                        uint32_t& r2, uint32_t& r3, uint32_t addr) {
    asm volatile("ldmatrix.sync.aligned.m8n8.x4.shared.b16 {%0,%1,%2,%3}, [%4];"
                 : "=r"(r0), "=r"(r1), "=r"(r2), "=r"(r3) : "r"(addr));
}
__device__ __forceinline__ uint32_t smem_u32(const void* p) {
    uint32_t a;
    asm("{ .reg .u64 t; cvta.to.shared.u64 t, %1; cvt.u32.u64 %0, t; }"
        : "=r"(a) : "l"(p));
    return a;
}
__device__ __forceinline__ void cpasync16(uint32_t dst, const void* src) {
    asm volatile("cp.async.cg.shared.global [%0], [%1], 16;"
                 :: "r"(dst), "l"(src) : "memory");
}
__device__ __forceinline__ void cp_commit() {
    asm volatile("cp.async.commit_group;" ::: "memory");
}
__device__ __forceinline__ void cp_wait2() {
    asm volatile("cp.async.wait_group 2;" ::: "memory");
}
// fast accurate tanh: 1 - 2/(exp(2x)+1); MUFU-based, rel err ~1e-6
__device__ __forceinline__ float fast_tanh(float x) {
    float e = __expf(2.f * x);
    return 1.f - __fdividef(2.f, e + 1.f);
}

// ---------------------------------------------------------------------------
// Kernel 0 (FUSED prep): block-range dispatch
//   [0, NPX)            : X fp32 -> fp16        (bandwidth-bound bulk)
//   [NPX, NPX+NPU)      : Ua -> UaT fp16        (hidden under prep_x)
//   [NPX+NPU, +NWAS)    : WaS = prev@Wa + Ba    (hidden under prep_x)
// ---------------------------------------------------------------------------
#define NPX  (M_TOTAL * DIM / (256 * 8))   // 16384
#define NPU  ((OUTD / 32) * (DIM / 32))    // 1024
#define NWAS (OUTD / 8)                    // 128

__global__ __launch_bounds__(256) void prep_all(
    const float* __restrict__ X, const float* __restrict__ Ua,
    const float* __restrict__ prev, const float* __restrict__ Wa,
    const float* __restrict__ Ba)
{
    __shared__ float buf[2400];   // union: prep_u 1056 floats; was 2112+288

    if (blockIdx.x < NPX) {
        // ---- prep_x ----
        size_t i = ((size_t)blockIdx.x * 256 + threadIdx.x) * 8;
        float4 a = *reinterpret_cast<const float4*>(X + i);
        float4 b = *reinterpret_cast<const float4*>(X + i + 4);
        uint4 u;
        u.x = pack_f16x2(a.x, a.y);
        u.y = pack_f16x2(a.z, a.w);
        u.z = pack_f16x2(b.x, b.y);
        u.w = pack_f16x2(b.z, b.w);
        *reinterpret_cast<uint4*>(&g_Xh[i]) = u;
    } else if (blockIdx.x < NPX + NPU) {
        // ---- prep_u: Ua [k][n] -> g_UhT [n][k] fp16 (32x32 tile) ----
        int id = blockIdx.x - NPX;
        int bx = (id & 31) * 32, by = (id >> 5) * 32;   // bx: n, by: k
        int tx = threadIdx.x & 31, ty = threadIdx.x >> 5;
        float (*t)[33] = reinterpret_cast<float (*)[33]>(buf);
        #pragma unroll
        for (int i = 0; i < 32; i += 8)
            t[ty + i][tx] = Ua[(size_t)(by + ty + i) * OUTD + bx + tx];
        __syncthreads();
        #pragma unroll
        for (int i = 0; i < 32; i += 8)
            g_UhT[(size_t)(bx + ty + i) * DIM + by + tx] =
                __float2half(t[tx][ty + i]);
    } else {
        // ---- was: WaS[b,o] = Ba[o] + sum_k prev[b,k] * Wa[k,o] ----
        int o0 = (blockIdx.x - NPX - NPU) * 8;
        int oo = threadIdx.x & 7;
        int bq = threadIdx.x >> 3;
        float (*ps)[33] = reinterpret_cast<float (*)[33]>(buf);         // 64x33
        float (*ws)[9]  = reinterpret_cast<float (*)[9]>(buf + 2112);   // 32x9

        float acc0 = 0.f, acc1 = 0.f;
        for (int k0 = 0; k0 < OUTD; k0 += 32) {
            #pragma unroll
            for (int j = 0; j < 8; ++j) {
                int e = threadIdx.x + j * 256;
                int bb = e >> 5, kk = e & 31;
                ps[bb][kk] = prev[bb * OUTD + k0 + kk];
            }
            {
                int kk = threadIdx.x >> 3, o = threadIdx.x & 7;
                ws[kk][o] = Wa[(size_t)(k0 + kk) * OUTD + o0 + o];
            }
            __syncthreads();
            #pragma unroll
            for (int kk = 0; kk < 32; ++kk) {
                float w = ws[kk][oo];
                acc0 = fmaf(ps[bq * 2 + 0][kk], w, acc0);
                acc1 = fmaf(ps[bq * 2 + 1][kk], w, acc1);
            }
            __syncthreads();
        }
        float bav = Ba[o0 + oo];
        g_WaS[(bq * 2 + 0) * OUTD + o0 + oo] = acc0 + bav;
        g_WaS[(bq * 2 + 1) * OUTD + o0 + oo] = acc1 + bav;
    }
}

// ---------------------------------------------------------------------------
// Kernel 1: fused GEMM  C = Xh @ UhT^T  (fp16 mma, fp32 accum)  [R12 exact]
// epilogue: partial[m, nchunk] = sum_n Va[n] * tanh(C[m,n] + WaS[b,n])
// BM=128, BN=128, BK=32, 256 threads, 8 warps (4M x 2N), warp tile 32x64.
// 4-stage cp.async ring + wait_group 2; all 12 LDSM hoisted before 32 HMMAs.
// At ~98% of the legacy mma.sync fp16 wall (512 MAC/cyc/SM) — do not touch.
// ---------------------------------------------------------------------------
#define BM 128
#define BN 128
#define BK 32
#define NKT (DIM / BK)     // 32
#define ROW_W 20           // u32 words per smem row (80 B, 16B multiple)
#define ROW_B 80
#define STG_W (128 * ROW_W)          // words per operand stage (2560)
#define STG_B (STG_W * 4)            // 10240 B
#define NSTG 4
#define GEMM_DYN_SMEM (2 * NSTG * STG_B)   // 81920 B

__global__ __launch_bounds__(256, 2) void attn_gemm_kernel(
    const float* __restrict__ Va)
{
    extern __shared__ __align__(16) uint32_t sm_[];
    uint32_t* As = sm_;                    // [4][128][ROW_W]
    uint32_t* Bs = sm_ + NSTG * STG_W;     // [4][128][ROW_W]
    __shared__ float sc[2][BM];
    __shared__ float vva[BN];
    __shared__ float wss[BN];

    const int tid = threadIdx.x;
    const int lane = tid & 31;
    const int wid = tid >> 5;
    const int wm = wid & 3;
    const int wn = wid >> 2;
    const int gid = lane >> 2;
    const int t4  = lane & 3;
    const int n0 = blockIdx.x * BN;
    const int m0 = blockIdx.y * BM;
    const int b  = m0 >> 9;

    const uint32_t As_u = smem_u32(As);
    const uint32_t Bs_u = smem_u32(Bs);

    // per-lane ldmatrix byte offsets (within a stage)
    const uint32_t offA = (uint32_t)((wm * 32 + (lane & 15)) * ROW_B
                                     + ((lane & 16) ? 16 : 0));
    const uint32_t offB = (uint32_t)((wn * 64 + (lane & 7) + ((lane & 16) ? 8 : 0)) * ROW_B
                                     + ((lane & 8) ? 16 : 0));

    // cp.async mapping: 512 16B-chunks per operand tile (128 rows x 4), 2/thread
    const int c_row = tid >> 1;           // 0..127 (two threads per row)
    const int c_ch0 = (tid & 1) * 2;      // chunks 0-1 or 2-3
    const __half* Xp = g_Xh + (size_t)(m0 + c_row) * DIM + c_ch0 * 8;
    const __half* Up = g_UhT + (size_t)(n0 + c_row) * DIM + c_ch0 * 8;
    const uint32_t a_dst0 = As_u + (uint32_t)(c_row * ROW_B + c_ch0 * 16);
    const uint32_t b_dst0 = Bs_u + (uint32_t)(c_row * ROW_B + c_ch0 * 16);

    auto issue_stage = [&](int kt, int s) {
        const __half* xs = Xp + kt * BK;
        const __half* us = Up + kt * BK;
        uint32_t ad = a_dst0 + (uint32_t)s * STG_B;
        uint32_t bd = b_dst0 + (uint32_t)s * STG_B;
        cpasync16(ad, xs);
        cpasync16(ad + 16, xs + 8);
        cpasync16(bd, us);
        cpasync16(bd + 16, us + 8);
    };

    // stage epilogue operands early (overlaps with pipeline fill)
    if (tid < BN) {
        vva[tid] = Va[n0 + tid];
        wss[tid] = g_WaS[b * OUTD + n0 + tid];
    }

    float acc[2][8][4];
    #pragma unroll
    for (int mi = 0; mi < 2; ++mi)
        #pragma unroll
        for (int ni = 0; ni < 8; ++ni)
            #pragma unroll
            for (int j = 0; j < 4; ++j) acc[mi][ni][j] = 0.f;

    // prologue: stages 0..2
    issue_stage(0, 0); cp_commit();
    issue_stage(1, 1); cp_commit();
    issue_stage(2, 2); cp_commit();

    for (int kt = 0; kt < NKT; ++kt) {
        cp_wait2();
        __syncthreads();

        if (kt + 3 < NKT) issue_stage(kt + 3, (kt + 3) & 3);
        cp_commit();

        const uint32_t Ab = As_u + (uint32_t)((kt & 3) * STG_B) + offA;
        const uint32_t Bb = Bs_u + (uint32_t)((kt & 3) * STG_B) + offB;

        // ---- load ALL fragments for both k16 steps first (12 LDSM) ----
        uint32_t af[2][2][4];    // [ks][mi][4]
        uint32_t bf[2][8][2];    // [ks][ni][2]
        #pragma unroll
        for (int ks = 0; ks < 2; ++ks) {
            #pragma unroll
            for (int mi = 0; mi < 2; ++mi)
                ldsm_x4(af[ks][mi][0], af[ks][mi][1], af[ks][mi][2], af[ks][mi][3],
                        Ab + (uint32_t)(mi * 16 * ROW_B + ks * 32));
            #pragma unroll
            for (int np = 0; np < 4; ++np)
                ldsm_x4(bf[ks][2 * np][0], bf[ks][2 * np][1],
                        bf[ks][2 * np + 1][0], bf[ks][2 * np + 1][1],
                        Bb + (uint32_t)(np * 16 * ROW_B + ks * 32));
        }
        // ---- then the 32 HMMAs back-to-back ----
        #pragma unroll
        for (int ks = 0; ks < 2; ++ks)
            #pragma unroll
            for (int mi = 0; mi < 2; ++mi)
                #pragma unroll
                for (int ni = 0; ni < 8; ++ni)
                    mma_f16(acc[mi][ni], af[ks][mi], bf[ks][ni]);
    }
    __syncthreads();

    // Epilogue: tanh + Va-dot, reduce per row
    float rowsum[2][2] = {{0.f, 0.f}, {0.f, 0.f}};
    #pragma unroll
    for (int mi = 0; mi < 2; ++mi) {
        #pragma unroll
        for (int ni = 0; ni < 8; ++ni) {
            #pragma unroll
            for (int j = 0; j < 4; ++j) {
                int nl = wn * 64 + ni * 8 + (t4 << 1) + (j & 1);
                float v = acc[mi][ni][j] + wss[nl];
                rowsum[mi][j >> 1] += fast_tanh(v) * vva[nl];
            }
        }
    }
    #pragma unroll
    for (int mi = 0; mi < 2; ++mi) {
        #pragma unroll
        for (int h = 0; h < 2; ++h) {
            float s = rowsum[mi][h];
            s += __shfl_xor_sync(0xffffffffu, s, 1);
            s += __shfl_xor_sync(0xffffffffu, s, 2);
            if (t4 == 0) {
                int r = wm * 32 + mi * 16 + gid + h * 8;
                sc[wn][r] = s;
            }
        }
    }
    __syncthreads();
    if (tid < BM) {
        g_partial[(size_t)(m0 + tid) * NCHUNKS + blockIdx.x] = sc[0][tid] + sc[1][tid];
    }
}

// ---------------------------------------------------------------------------
// Kernel 2: FUSED relu+softmax+context (R14 exact).
// grid (64, 8) x 256. Each block recomputes the 512-wide softmax for its
// batch row from g_partial (L2-resident), then the weighted sum over 128 d.
// ---------------------------------------------------------------------------
__global__ __launch_bounds__(256) void context_kernel(float* __restrict__ out)
{
    int bb = blockIdx.x;
    int d0 = blockIdx.y * 128;
    int o  = threadIdx.x & 15;    // 16 octs -> 128 d
    int tg = threadIdx.x >> 4;    // 16 t-groups of 32

    __shared__ float w[TSTEPS];
    __shared__ float part[16][16][8];
    __shared__ float red[8];
    __shared__ float smax, ssum;

    // ---- relu(partial-sum) for two timesteps per thread ----
    int t0 = threadIdx.x, t1 = threadIdx.x + 256;
    const float* p0 = g_partial + ((size_t)bb * TSTEPS + t0) * NCHUNKS;
    const float* p1 = g_partial + ((size_t)bb * TSTEPS + t1) * NCHUNKS;
    float s0 = 0.f, s1 = 0.f;
    #pragma unroll
    for (int i = 0; i < NCHUNKS; ++i) { s0 += p0[i]; s1 += p1[i]; }
    s0 = fmaxf(s0, 0.f);
    s1 = fmaxf(s1, 0.f);

    // ---- block softmax over 512 values ----
    float m = fmaxf(s0, s1);
    #pragma unroll
    for (int off = 16; off; off >>= 1)
        m = fmaxf(m, __shfl_xor_sync(0xffffffffu, m, off));
    if ((threadIdx.x & 31) == 0) red[threadIdx.x >> 5] = m;
    __syncthreads();
    if (threadIdx.x == 0) {
        float v = red[0];
        #pragma unroll
        for (int i = 1; i < 8; ++i) v = fmaxf(v, red[i]);
        smax = v;
    }
    __syncthreads();

    float e0 = __expf(s0 - smax);
    float e1 = __expf(s1 - smax);
    float q = e0 + e1;
    #pragma unroll
    for (int off = 16; off; off >>= 1)
        q += __shfl_xor_sync(0xffffffffu, q, off);
    if ((threadIdx.x & 31) == 0) red[threadIdx.x >> 5] = q;
    __syncthreads();
    if (threadIdx.x == 0) {
        float v = 0.f;
        #pragma unroll
        for (int i = 0; i < 8; ++i) v += red[i];
        ssum = v;
    }
    __syncthreads();

    float inv = __fdividef(1.f, ssum);
    w[t0] = e0 * inv;
    w[t1] = e1 * inv;
    __syncthreads();

    // ---- weighted sum over timesteps ----
    const __half* xp = g_Xh + (size_t)bb * TSTEPS * DIM + d0 + o * 8;
    float a0 = 0.f, a1 = 0.f, a2 = 0.f, a3 = 0.f,
          a4 = 0.f, a5 = 0.f, a6 = 0.f, a7 = 0.f;
    int tb = tg * 32;
    #pragma unroll 4
    for (int t = 0; t < 32; ++t) {
        uint4 v = *reinterpret_cast<const uint4*>(xp + (size_t)(tb + t) * DIM);
        float ww = w[tb + t];
        float2 f;
        f = __half22float2(*reinterpret_cast<__half2*>(&v.x));
        a0 = fmaf(f.x, ww, a0); a1 = fmaf(f.y, ww, a1);
        f = __half22float2(*reinterpret_cast<__half2*>(&v.y));
        a2 = fmaf(f.x, ww, a2); a3 = fmaf(f.y, ww, a3);
        f = __half22float2(*reinterpret_cast<__half2*>(&v.z));
        a4 = fmaf(f.x, ww, a4); a5 = fmaf(f.y, ww, a5);
        f = __half22float2(*reinterpret_cast<__half2*>(&v.w));
        a6 = fmaf(f.x, ww, a6); a7 = fmaf(f.y, ww, a7);
    }
    part[tg][o][0] = a0; part[tg][o][1] = a1;
    part[tg][o][2] = a2; part[tg][o][3] = a3;
    part[tg][o][4] = a4; part[tg][o][5] = a5;
    part[tg][o][6] = a6; part[tg][o][7] = a7;
    __syncthreads();
    if (threadIdx.x < 128) {
        int d = threadIdx.x;
        float s = 0.f;
        #pragma unroll
        for (int g = 0; g < 16; ++g) s += part[g][d >> 3][d & 7];
        out[bb * DIM + d0 + d] = s;
    }
}

// ---------------------------------------------------------------------------
extern "C" void kernel_launch(void* const* d_in, const int* in_sizes, int n_in,
                              void* d_out, int out_size)
{
    const float* inputs = (const float*)d_in[0];
    const float* prev   = (const float*)d_in[1];
    const float* Wa     = (const float*)d_in[2];
    const float* Ua     = (const float*)d_in[3];
    const float* Va     = (const float*)d_in[4];
    const float* Ba     = (const float*)d_in[5];
    float* out = (float*)d_out;

    cudaFuncSetAttribute(attn_gemm_kernel,
                         cudaFuncAttributeMaxDynamicSharedMemorySize,
                         GEMM_DYN_SMEM);

    prep_all<<<NPX + NPU + NWAS, 256>>>(inputs, Ua, prev, Wa, Ba);
    attn_gemm_kernel<<<dim3(NCHUNKS, M_TOTAL / BM), 256, GEMM_DYN_SMEM>>>(Va);
    context_kernel<<<dim3(BATCH, DIM / 128), 256>>>(out);
}

// round 16
// speedup vs baseline: 1.0640x; 1.0640x over previous
#include <cuda_runtime.h>
#include <cuda_fp16.h>
#include <cstdint>
#include <cmath>

// Problem constants
#define BATCH 64
#define TSTEPS 512
#define DIM 1024
#define OUTD 1024
#define M_TOTAL (BATCH * TSTEPS)   // 32768
#define NCHUNKS 8                  // N / BN

// Scratch (device globals: no allocations allowed)
__device__ __half g_Xh[(size_t)M_TOTAL * DIM];   // fp16 copy of inputs (64 MB)
__device__ __half g_UhT[(size_t)OUTD * DIM];     // Ua transposed, fp16 [n][k]
__device__ float g_WaS[BATCH * OUTD];            // prev@Wa + Ba
__device__ float g_partial[M_TOTAL * NCHUNKS];   // per-(row, n-chunk) partial

__device__ __forceinline__ uint32_t pack_f16x2(float lo, float hi) {
    uint32_t r;
    asm("cvt.rn.f16x2.f32 %0, %1, %2;" : "=r"(r) : "f"(hi), "f"(lo));
    return r;
}
__device__ __forceinline__ void mma_f16(float* c, const uint32_t* a, const uint32_t* b) {
    asm("mma.sync.aligned.m16n8k16.row.col.f32.f16.f16.f32 "
        "{%0,%1,%2,%3}, {%4,%5,%6,%7}, {%8,%9}, {%0,%1,%2,%3};"
        : "+f"(c[0]), "+f"(c[1]), "+f"(c[2]), "+f"(c[3])
        : "r"(a[0]), "r"(a[1]), "r"(a[2]), "r"(a[3]), "r"(b[0]), "r"(b[1]));
}
__device__ __forceinline__ void ldsm_x4(uint32_t& r0, uint32_t& r1,
                                        uint32_t& r2, uint32_t& r3, uint32_t addr) {
    asm volatile("ldmatrix.sync.aligned.m8n8.x4.shared.b16 {%0,%1,%2,%3}, [%4];"
                 : "=r"(r0), "=r"(r1), "=r"(r2), "=r"(r3) : "r"(addr));
}
__device__ __forceinline__ uint32_t smem_u32(const void* p) {
    uint32_t a;
    asm("{ .reg .u64 t; cvta.to.shared.u64 t, %1; cvt.u32.u64 %0, t; }"
        : "=r"(a) : "l"(p));
    return a;
}
__device__ __forceinline__ void cpasync16(uint32_t dst, const void* src) {
    asm volatile("cp.async.cg.shared.global [%0], [%1], 16;"
                 :: "r"(dst), "l"(src) : "memory");
}
__device__ __forceinline__ void cp_commit() {
    asm volatile("cp.async.commit_group;" ::: "memory");
}
__device__ __forceinline__ void cp_wait2() {
    asm volatile("cp.async.wait_group 2;" ::: "memory");
}
// fast accurate tanh: 1 - 2/(exp(2x)+1); MUFU-based, rel err ~1e-6
__device__ __forceinline__ float fast_tanh(float x) {
    float e = __expf(2.f * x);
    return 1.f - __fdividef(2.f, e + 1.f);
}

// ---------------------------------------------------------------------------
// Kernel 0 (FUSED prep): block-range dispatch, LONG BLOCKS FIRST so the
// latency-bound was/prep_u work runs concurrently under the prep_x stream:
//   [0, NWAS)                 : WaS = prev@Wa + Ba   (longest, wave 1)
//   [NWAS, NWAS+NPU)          : Ua -> UaT fp16
//   [NWAS+NPU, +NPX)          : X fp32 -> fp16       (bandwidth-bound bulk)
// ---------------------------------------------------------------------------
#define NPX  (M_TOTAL * DIM / (256 * 8))   // 16384
#define NPU  ((OUTD / 32) * (DIM / 32))    // 1024
#define NWAS (OUTD / 8)                    // 128

__global__ __launch_bounds__(256) void prep_all(
    const float* __restrict__ X, const float* __restrict__ Ua,
    const float* __restrict__ prev, const float* __restrict__ Wa,
    const float* __restrict__ Ba)
{
    __shared__ float buf[2400];   // union: prep_u 1056 floats; was 2112+288

    if (blockIdx.x >= NWAS + NPU) {
        // ---- prep_x ----
        size_t i = ((size_t)(blockIdx.x - NWAS - NPU) * 256 + threadIdx.x) * 8;
        float4 a = *reinterpret_cast<const float4*>(X + i);
        float4 b = *reinterpret_cast<const float4*>(X + i + 4);
        uint4 u;
        u.x = pack_f16x2(a.x, a.y);
        u.y = pack_f16x2(a.z, a.w);
        u.z = pack_f16x2(b.x, b.y);
        u.w = pack_f16x2(b.z, b.w);
        *reinterpret_cast<uint4*>(&g_Xh[i]) = u;
    } else if (blockIdx.x >= NWAS) {
        // ---- prep_u: Ua [k][n] -> g_UhT [n][k] fp16 (32x32 tile) ----
        int id = blockIdx.x - NWAS;
        int bx = (id & 31) * 32, by = (id >> 5) * 32;   // bx: n, by: k
        int tx = threadIdx.x & 31, ty = threadIdx.x >> 5;
        float (*t)[33] = reinterpret_cast<float (*)[33]>(buf);
        #pragma unroll
        for (int i = 0; i < 32; i += 8)
            t[ty + i][tx] = Ua[(size_t)(by + ty + i) * OUTD + bx + tx];
        __syncthreads();
        #pragma unroll
        for (int i = 0; i < 32; i += 8)
            g_UhT[(size_t)(bx + ty + i) * DIM + by + tx] =
                __float2half(t[tx][ty + i]);
    } else {
        // ---- was: WaS[b,o] = Ba[o] + sum_k prev[b,k] * Wa[k,o] ----
        int o0 = blockIdx.x * 8;
        int oo = threadIdx.x & 7;
        int bq = threadIdx.x >> 3;
        float (*ps)[33] = reinterpret_cast<float (*)[33]>(buf);         // 64x33
        float (*ws)[9]  = reinterpret_cast<float (*)[9]>(buf + 2112);   // 32x9

        float acc0 = 0.f, acc1 = 0.f;
        for (int k0 = 0; k0 < OUTD; k0 += 32) {
            #pragma unroll
            for (int j = 0; j < 8; ++j) {
                int e = threadIdx.x + j * 256;
                int bb = e >> 5, kk = e & 31;
                ps[bb][kk] = prev[bb * OUTD + k0 + kk];
            }
            {
                int kk = threadIdx.x >> 3, o = threadIdx.x & 7;
                ws[kk][o] = Wa[(size_t)(k0 + kk) * OUTD + o0 + o];
            }
            __syncthreads();
            #pragma unroll
            for (int kk = 0; kk < 32; ++kk) {
                float w = ws[kk][oo];
                acc0 = fmaf(ps[bq * 2 + 0][kk], w, acc0);
                acc1 = fmaf(ps[bq * 2 + 1][kk], w, acc1);
            }
            __syncthreads();
        }
        float bav = Ba[o0 + oo];
        g_WaS[(bq * 2 + 0) * OUTD + o0 + oo] = acc0 + bav;
        g_WaS[(bq * 2 + 1) * OUTD + o0 + oo] = acc1 + bav;
    }
}

// ---------------------------------------------------------------------------
// Kernel 1: fused GEMM  C = Xh @ UhT^T  (fp16 mma, fp32 accum)  [R12 exact]
// epilogue: partial[m, nchunk] = sum_n Va[n] * tanh(C[m,n] + WaS[b,n])
// BM=128, BN=128, BK=32, 256 threads, 8 warps (4M x 2N), warp tile 32x64.
// 4-stage cp.async ring + wait_group 2; all 12 LDSM hoisted before 32 HMMAs.
// At ~98% of the legacy mma.sync fp16 wall (512 MAC/cyc/SM) — do not touch.
// ---------------------------------------------------------------------------
#define BM 128
#define BN 128
#define BK 32
#define NKT (DIM / BK)     // 32
#define ROW_W 20           // u32 words per smem row (80 B, 16B multiple)
#define ROW_B 80
#define STG_W (128 * ROW_W)          // words per operand stage (2560)
#define STG_B (STG_W * 4)            // 10240 B
#define NSTG 4
#define GEMM_DYN_SMEM (2 * NSTG * STG_B)   // 81920 B

__global__ __launch_bounds__(256, 2) void attn_gemm_kernel(
    const float* __restrict__ Va)
{
    extern __shared__ __align__(16) uint32_t sm_[];
    uint32_t* As = sm_;                    // [4][128][ROW_W]
    uint32_t* Bs = sm_ + NSTG * STG_W;     // [4][128][ROW_W]
    __shared__ float sc[2][BM];
    __shared__ float vva[BN];
    __shared__ float wss[BN];

    const int tid = threadIdx.x;
    const int lane = tid & 31;
    const int wid = tid >> 5;
    const int wm = wid & 3;
    const int wn = wid >> 2;
    const int gid = lane >> 2;
    const int t4  = lane & 3;
    const int n0 = blockIdx.x * BN;
    const int m0 = blockIdx.y * BM;
    const int b  = m0 >> 9;

    const uint32_t As_u = smem_u32(As);
    const uint32_t Bs_u = smem_u32(Bs);

    // per-lane ldmatrix byte offsets (within a stage)
    const uint32_t offA = (uint32_t)((wm * 32 + (lane & 15)) * ROW_B
                                     + ((lane & 16) ? 16 : 0));
    const uint32_t offB = (uint32_t)((wn * 64 + (lane & 7) + ((lane & 16) ? 8 : 0)) * ROW_B
                                     + ((lane & 8) ? 16 : 0));

    // cp.async mapping: 512 16B-chunks per operand tile (128 rows x 4), 2/thread
    const int c_row = tid >> 1;           // 0..127 (two threads per row)
    const int c_ch0 = (tid & 1) * 2;      // chunks 0-1 or 2-3
    const __half* Xp = g_Xh + (size_t)(m0 + c_row) * DIM + c_ch0 * 8;
    const __half* Up = g_UhT + (size_t)(n0 + c_row) * DIM + c_ch0 * 8;
    const uint32_t a_dst0 = As_u + (uint32_t)(c_row * ROW_B + c_ch0 * 16);
    const uint32_t b_dst0 = Bs_u + (uint32_t)(c_row * ROW_B + c_ch0 * 16);

    auto issue_stage = [&](int kt, int s) {
        const __half* xs = Xp + kt * BK;
        const __half* us = Up + kt * BK;
        uint32_t ad = a_dst0 + (uint32_t)s * STG_B;
        uint32_t bd = b_dst0 + (uint32_t)s * STG_B;
        cpasync16(ad, xs);
        cpasync16(ad + 16, xs + 8);
        cpasync16(bd, us);
        cpasync16(bd + 16, us + 8);
    };

    // stage epilogue operands early (overlaps with pipeline fill)
    if (tid < BN) {
        vva[tid] = Va[n0 + tid];
        wss[tid] = g_WaS[b * OUTD + n0 + tid];
    }

    float acc[2][8][4];
    #pragma unroll
    for (int mi = 0; mi < 2; ++mi)
        #pragma unroll
        for (int ni = 0; ni < 8; ++ni)
            #pragma unroll
            for (int j = 0; j < 4; ++j) acc[mi][ni][j] = 0.f;

    // prologue: stages 0..2
    issue_stage(0, 0); cp_commit();
    issue_stage(1, 1); cp_commit();
    issue_stage(2, 2); cp_commit();

    for (int kt = 0; kt < NKT; ++kt) {
        cp_wait2();
        __syncthreads();

        if (kt + 3 < NKT) issue_stage(kt + 3, (kt + 3) & 3);
        cp_commit();

        const uint32_t Ab = As_u + (uint32_t)((kt & 3) * STG_B) + offA;
        const uint32_t Bb = Bs_u + (uint32_t)((kt & 3) * STG_B) + offB;

        // ---- load ALL fragments for both k16 steps first (12 LDSM) ----
        uint32_t af[2][2][4];    // [ks][mi][4]
        uint32_t bf[2][8][2];    // [ks][ni][2]
        #pragma unroll
        for (int ks = 0; ks < 2; ++ks) {
            #pragma unroll
            for (int mi = 0; mi < 2; ++mi)
                ldsm_x4(af[ks][mi][0], af[ks][mi][1], af[ks][mi][2], af[ks][mi][3],
                        Ab + (uint32_t)(mi * 16 * ROW_B + ks * 32));
            #pragma unroll
            for (int np = 0; np < 4; ++np)
                ldsm_x4(bf[ks][2 * np][0], bf[ks][2 * np][1],
                        bf[ks][2 * np + 1][0], bf[ks][2 * np + 1][1],
                        Bb + (uint32_t)(np * 16 * ROW_B + ks * 32));
        }
        // ---- then the 32 HMMAs back-to-back ----
        #pragma unroll
        for (int ks = 0; ks < 2; ++ks)
            #pragma unroll
            for (int mi = 0; mi < 2; ++mi)
                #pragma unroll
                for (int ni = 0; ni < 8; ++ni)
                    mma_f16(acc[mi][ni], af[ks][mi], bf[ks][ni]);
    }
    __syncthreads();

    // Epilogue: tanh + Va-dot, reduce per row
    float rowsum[2][2] = {{0.f, 0.f}, {0.f, 0.f}};
    #pragma unroll
    for (int mi = 0; mi < 2; ++mi) {
        #pragma unroll
        for (int ni = 0; ni < 8; ++ni) {
            #pragma unroll
            for (int j = 0; j < 4; ++j) {
                int nl = wn * 64 + ni * 8 + (t4 << 1) + (j & 1);
                float v = acc[mi][ni][j] + wss[nl];
                rowsum[mi][j >> 1] += fast_tanh(v) * vva[nl];
            }
        }
    }
    #pragma unroll
    for (int mi = 0; mi < 2; ++mi) {
        #pragma unroll
        for (int h = 0; h < 2; ++h) {
            float s = rowsum[mi][h];
            s += __shfl_xor_sync(0xffffffffu, s, 1);
            s += __shfl_xor_sync(0xffffffffu, s, 2);
            if (t4 == 0) {
                int r = wm * 32 + mi * 16 + gid + h * 8;
                sc[wn][r] = s;
            }
        }
    }
    __syncthreads();
    if (tid < BM) {
        g_partial[(size_t)(m0 + tid) * NCHUNKS + blockIdx.x] = sc[0][tid] + sc[1][tid];
    }
}

// ---------------------------------------------------------------------------
// Kernel 2: FUSED relu+softmax+context (R14 exact).
// grid (64, 8) x 256. Each block recomputes the 512-wide softmax for its
// batch row from g_partial (L2-resident), then the weighted sum over 128 d.
// ---------------------------------------------------------------------------
__global__ __launch_bounds__(256) void context_kernel(float* __restrict__ out)
{
    int bb = blockIdx.x;
    int d0 = blockIdx.y * 128;
    int o  = threadIdx.x & 15;    // 16 octs -> 128 d
    int tg = threadIdx.x >> 4;    // 16 t-groups of 32

    __shared__ float w[TSTEPS];
    __shared__ float part[16][16][8];
    __shared__ float red[8];
    __shared__ float smax, ssum;

    // ---- relu(partial-sum) for two timesteps per thread ----
    int t0 = threadIdx.x, t1 = threadIdx.x + 256;
    const float* p0 = g_partial + ((size_t)bb * TSTEPS + t0) * NCHUNKS;
    const float* p1 = g_partial + ((size_t)bb * TSTEPS + t1) * NCHUNKS;
    float s0 = 0.f, s1 = 0.f;
    #pragma unroll
    for (int i = 0; i < NCHUNKS; ++i) { s0 += p0[i]; s1 += p1[i]; }
    s0 = fmaxf(s0, 0.f);
    s1 = fmaxf(s1, 0.f);

    // ---- block softmax over 512 values ----
    float m = fmaxf(s0, s1);
    #pragma unroll
    for (int off = 16; off; off >>= 1)
        m = fmaxf(m, __shfl_xor_sync(0xffffffffu, m, off));
    if ((threadIdx.x & 31) == 0) red[threadIdx.x >> 5] = m;
    __syncthreads();
    if (threadIdx.x == 0) {
        float v = red[0];
        #pragma unroll
        for (int i = 1; i < 8; ++i) v = fmaxf(v, red[i]);
        smax = v;
    }
    __syncthreads();

    float e0 = __expf(s0 - smax);
    float e1 = __expf(s1 - smax);
    float q = e0 + e1;
    #pragma unroll
    for (int off = 16; off; off >>= 1)
        q += __shfl_xor_sync(0xffffffffu, q, off);
    if ((threadIdx.x & 31) == 0) red[threadIdx.x >> 5] = q;
    __syncthreads();
    if (threadIdx.x == 0) {
        float v = 0.f;
        #pragma unroll
        for (int i = 0; i < 8; ++i) v += red[i];
        ssum = v;
    }
    __syncthreads();

    float inv = __fdividef(1.f, ssum);
    w[t0] = e0 * inv;
    w[t1] = e1 * inv;
    __syncthreads();

    // ---- weighted sum over timesteps ----
    const __half* xp = g_Xh + (size_t)bb * TSTEPS * DIM + d0 + o * 8;
    float a0 = 0.f, a1 = 0.f, a2 = 0.f, a3 = 0.f,
          a4 = 0.f, a5 = 0.f, a6 = 0.f, a7 = 0.f;
    int tb = tg * 32;
    #pragma unroll 4
    for (int t = 0; t < 32; ++t) {
        uint4 v = *reinterpret_cast<const uint4*>(xp + (size_t)(tb + t) * DIM);
        float ww = w[tb + t];
        float2 f;
        f = __half22float2(*reinterpret_cast<__half2*>(&v.x));
        a0 = fmaf(f.x, ww, a0); a1 = fmaf(f.y, ww, a1);
        f = __half22float2(*reinterpret_cast<__half2*>(&v.y));
        a2 = fmaf(f.x, ww, a2); a3 = fmaf(f.y, ww, a3);
        f = __half22float2(*reinterpret_cast<__half2*>(&v.z));
        a4 = fmaf(f.x, ww, a4); a5 = fmaf(f.y, ww, a5);
        f = __half22float2(*reinterpret_cast<__half2*>(&v.w));
        a6 = fmaf(f.x, ww, a6); a7 = fmaf(f.y, ww, a7);
    }
    part[tg][o][0] = a0; part[tg][o][1] = a1;
    part[tg][o][2] = a2; part[tg][o][3] = a3;
    part[tg][o][4] = a4; part[tg][o][5] = a5;
    part[tg][o][6] = a6; part[tg][o][7] = a7;
    __syncthreads();
    if (threadIdx.x < 128) {
        int d = threadIdx.x;
        float s = 0.f;
        #pragma unroll
        for (int g = 0; g < 16; ++g) s += part[g][d >> 3][d & 7];
        out[bb * DIM + d0 + d] = s;
    }
}

// ---------------------------------------------------------------------------
extern "C" void kernel_launch(void* const* d_in, const int* in_sizes, int n_in,
                              void* d_out, int out_size)
{
    const float* inputs = (const float*)d_in[0];
    const float* prev   = (const float*)d_in[1];
    const float* Wa     = (const float*)d_in[2];
    const float* Ua     = (const float*)d_in[3];
    const float* Va     = (const float*)d_in[4];
    const float* Ba     = (const float*)d_in[5];
    float* out = (float*)d_out;

    cudaFuncSetAttribute(attn_gemm_kernel,
                         cudaFuncAttributeMaxDynamicSharedMemorySize,
                         GEMM_DYN_SMEM);

    prep_all<<<NWAS + NPU + NPX, 256>>>(inputs, Ua, prev, Wa, Ba);
    attn_gemm_kernel<<<dim3(NCHUNKS, M_TOTAL / BM), 256, GEMM_DYN_SMEM>>>(Va);
    context_kernel<<<dim3(BATCH, DIM / 128), 256>>>(out);
}